// round 1
// baseline (speedup 1.0000x reference)
#include <cuda_runtime.h>
#include <cuda_bf16.h>
#include <math.h>

#define N_NODES 100000
#define E_EDGES 1600000
#define G_GR    2000
#define P_PAIRS 4096
#define UDIM    128

// ---------------- scratch (static device globals; no allocation) -------------
__device__ float d_g[N_NODES * UDIM];     // 51.2 MB ping
__device__ float d_h[N_NODES * UDIM];     // 51.2 MB pong
__device__ int   d_counts[N_NODES];
__device__ int   d_startA[N_NODES];
__device__ int   d_cursor[N_NODES];
__device__ int   d_bsums[128];
__device__ int   d_boffs[128];
__device__ float d_dinv[N_NODES];
__device__ int   d_esrc[E_EDGES];         // edge srcs sorted by dst (CSR payload)
__device__ float d_gsum[G_GR];
__device__ int   d_gcnt[G_GR];
__device__ float d_util[G_GR];

// ---------------- init / CSR build ------------------------------------------
__global__ void k_zero() {
    int i = blockIdx.x * blockDim.x + threadIdx.x;
    if (i < N_NODES) d_counts[i] = 0;
    if (i < G_GR) { d_gsum[i] = 0.0f; d_gcnt[i] = 0; }
}

__global__ void k_count(const int* __restrict__ ei) {
    int e = blockIdx.x * blockDim.x + threadIdx.x;
    if (e < E_EDGES) atomicAdd(&d_counts[ei[E_EDGES + e]], 1);
}

__global__ void k_scan1(int n) {
    __shared__ int wsum[32];
    int i = blockIdx.x * 1024 + threadIdx.x;
    int lane = threadIdx.x & 31, w = threadIdx.x >> 5;
    int v = (i < n) ? d_counts[i] : 0;
    int x = v;
#pragma unroll
    for (int o = 1; o < 32; o <<= 1) {
        int y = __shfl_up_sync(0xffffffffu, x, o);
        if (lane >= o) x += y;
    }
    if (lane == 31) wsum[w] = x;
    __syncthreads();
    if (w == 0) {
        int s = wsum[lane];
        int xx = s;
#pragma unroll
        for (int o = 1; o < 32; o <<= 1) {
            int y = __shfl_up_sync(0xffffffffu, xx, o);
            if (lane >= o) xx += y;
        }
        if (lane == 31) d_bsums[blockIdx.x] = xx;   // block total
        wsum[lane] = xx - s;                        // exclusive warp offset
    }
    __syncthreads();
    int excl = x - v + wsum[w];
    if (i < n) d_startA[i] = excl;
}

__global__ void k_scan2(int nb) {
    __shared__ int wsum[4];
    int t = threadIdx.x, lane = t & 31, w = t >> 5;
    int v = (t < nb) ? d_bsums[t] : 0;
    int x = v;
#pragma unroll
    for (int o = 1; o < 32; o <<= 1) {
        int y = __shfl_up_sync(0xffffffffu, x, o);
        if (lane >= o) x += y;
    }
    if (lane == 31) wsum[w] = x;
    __syncthreads();
    if (t == 0) {
        int a = 0;
#pragma unroll
        for (int i = 0; i < 4; i++) { int tmp = wsum[i]; wsum[i] = a; a += tmp; }
    }
    __syncthreads();
    if (t < nb) d_boffs[t] = x - v + wsum[w];
}

__global__ void k_scan3(const int* __restrict__ batch) {
    int i = blockIdx.x * blockDim.x + threadIdx.x;
    if (i < N_NODES) {
        int s = d_startA[i] + d_boffs[i >> 10];
        d_startA[i] = s;
        d_cursor[i] = s;
        d_dinv[i] = rsqrtf((float)d_counts[i] + 1.0f);
        atomicAdd(&d_gcnt[batch[i]], 1);
    }
}

__global__ void k_fill(const int* __restrict__ ei) {
    int e = blockIdx.x * blockDim.x + threadIdx.x;
    if (e < E_EDGES) {
        int s = ei[e];
        int d = ei[E_EDGES + e];
        int p = atomicAdd(&d_cursor[d], 1);
        d_esrc[p] = s;
    }
}

// ---------------- GEMMs -----------------------------------------------------
// first layer: g = dinv * (x[N,9] @ W_in[9,128])
__global__ void k_gemm_in(const float* __restrict__ x, const float* __restrict__ W,
                          float* __restrict__ g) {
    __shared__ float Ws[9 * 128];
    for (int i = threadIdx.x; i < 9 * 128; i += 128) Ws[i] = W[i];
    __syncthreads();
    int j = threadIdx.x;
    for (int row = blockIdx.x; row < N_NODES; row += gridDim.x) {
        float acc = 0.0f;
#pragma unroll
        for (int k = 0; k < 9; k++)
            acc += __ldg(&x[row * 9 + k]) * Ws[k * 128 + j];
        g[row * 128 + j] = d_dinv[row] * acc;
    }
}

// 128x128 GEMM. MODE 0: C = dinv*(A@W)   MODE 1: C = tanh(A@W + bias)
template <int MODE>
__global__ void k_gemm128(const float* __restrict__ A, const float* __restrict__ W,
                          const float* __restrict__ bias, float* __restrict__ C) {
    extern __shared__ float sm[];
    float* As = sm;              // 64 x 132 (padded)
    float* Ws = sm + 64 * 132;   // 128 x 128
    const int t = threadIdx.x;   // 256 threads
    const int row0 = blockIdx.x * 64;

    const float4* W4 = (const float4*)W;
    float4* Ws4 = (float4*)Ws;
    for (int i = t; i < 128 * 32; i += 256) Ws4[i] = W4[i];

    const float4* A4 = (const float4*)A;
    for (int i = t; i < 64 * 32; i += 256) {
        int r = i >> 5, c4 = i & 31;
        float4 v;
        if (row0 + r < N_NODES) v = A4[(size_t)(row0 + r) * 32 + c4];
        else v = make_float4(0.f, 0.f, 0.f, 0.f);
        *((float4*)&As[r * 132 + c4 * 4]) = v;
    }
    __syncthreads();

    const int tr4 = (t >> 4) * 4;   // 4 rows per thread
    const int tc8 = (t & 15) * 8;   // 8 cols per thread

    float acc[4][8];
#pragma unroll
    for (int i = 0; i < 4; i++)
#pragma unroll
        for (int j = 0; j < 8; j++) acc[i][j] = 0.0f;

#pragma unroll 4
    for (int k = 0; k < 128; k++) {
        float a0 = As[(tr4 + 0) * 132 + k];
        float a1 = As[(tr4 + 1) * 132 + k];
        float a2 = As[(tr4 + 2) * 132 + k];
        float a3 = As[(tr4 + 3) * 132 + k];
        float4 w0 = *(const float4*)&Ws[k * 128 + tc8];
        float4 w1 = *(const float4*)&Ws[k * 128 + tc8 + 4];
        float wv[8] = {w0.x, w0.y, w0.z, w0.w, w1.x, w1.y, w1.z, w1.w};
#pragma unroll
        for (int j = 0; j < 8; j++) {
            acc[0][j] += a0 * wv[j];
            acc[1][j] += a1 * wv[j];
            acc[2][j] += a2 * wv[j];
            acc[3][j] += a3 * wv[j];
        }
    }

    float bb[8];
    if (MODE == 1) {
#pragma unroll
        for (int j = 0; j < 8; j++) bb[j] = __ldg(&bias[tc8 + j]);
    }

#pragma unroll
    for (int i = 0; i < 4; i++) {
        int r = row0 + tr4 + i;
        if (r < N_NODES) {
            float o[8];
            if (MODE == 0) {
                float s = d_dinv[r];
#pragma unroll
                for (int j = 0; j < 8; j++) o[j] = acc[i][j] * s;
            } else {
#pragma unroll
                for (int j = 0; j < 8; j++) o[j] = tanhf(acc[i][j] + bb[j]);
            }
            *(float4*)&C[(size_t)r * 128 + tc8]     = make_float4(o[0], o[1], o[2], o[3]);
            *(float4*)&C[(size_t)r * 128 + tc8 + 4] = make_float4(o[4], o[5], o[6], o[7]);
        }
    }
}

// ---------------- edge aggregation ------------------------------------------
// h[d] = tanh( dinv[d] * ( g[d] + sum_{e in CSR(d)} g[src_e] ) + b )
__global__ void k_agg(const float* __restrict__ gbuf, const float* __restrict__ bias,
                      float* __restrict__ hout) {
    int gw = (blockIdx.x * blockDim.x + threadIdx.x) >> 5;
    int lane = threadIdx.x & 31;
    if (gw >= N_NODES) return;
    int d = gw;

    const float4* g4 = (const float4*)gbuf;
    float4 acc = g4[(size_t)d * 32 + lane];

    int s0 = d_startA[d];
    int cnt = d_counts[d];
    for (int base = 0; base < cnt; base += 32) {
        int s = (base + lane < cnt) ? d_esrc[s0 + base + lane] : 0;
        int m = min(32, cnt - base);
        for (int i = 0; i < m; i++) {
            int ss = __shfl_sync(0xffffffffu, s, i);
            float4 v = g4[(size_t)ss * 32 + lane];
            acc.x += v.x; acc.y += v.y; acc.z += v.z; acc.w += v.w;
        }
    }
    float di = d_dinv[d];
    float4 b = ((const float4*)bias)[lane];
    float4 o;
    o.x = tanhf(di * acc.x + b.x);
    o.y = tanhf(di * acc.y + b.y);
    o.z = tanhf(di * acc.z + b.z);
    o.w = tanhf(di * acc.w + b.w);
    ((float4*)hout)[(size_t)d * 32 + lane] = o;
}

// ---------------- head: Wf2(128->32) tanh, Wf3(32->1), per-graph sum --------
__global__ void k_final(const float* __restrict__ h2, const float* __restrict__ Wf2,
                        const float* __restrict__ bf2, const float* __restrict__ Wf3,
                        const float* __restrict__ bf3, const int* __restrict__ batch) {
    __shared__ float Wf2s[128 * 32];
    __shared__ float Hs[8][132];
    __shared__ float bf2s[32];
    __shared__ float wf3s[32];
    int t = threadIdx.x;
    for (int i = t; i < 128 * 32; i += 256) Wf2s[i] = Wf2[i];
    if (t < 32) { bf2s[t] = bf2[t]; wf3s[t] = Wf3[t]; }

    int nodeBase = blockIdx.x * 8;
    for (int i = t; i < 8 * 32; i += 256) {
        int r = i >> 5, c4 = i & 31;
        int nd = nodeBase + r;
        float4 v = make_float4(0.f, 0.f, 0.f, 0.f);
        if (nd < N_NODES) v = ((const float4*)h2)[(size_t)nd * 32 + c4];
        *((float4*)&Hs[r][c4 * 4]) = v;
    }
    __syncthreads();

    int lane = t & 31, w = t >> 5;
    int node = nodeBase + w;
    if (node < N_NODES) {
        float acc = 0.0f;
#pragma unroll 8
        for (int k = 0; k < 128; k++) acc += Hs[w][k] * Wf2s[k * 32 + lane];
        float tt = tanhf(acc + bf2s[lane]);
        float p = tt * wf3s[lane];
#pragma unroll
        for (int o = 16; o > 0; o >>= 1) p += __shfl_down_sync(0xffffffffu, p, o);
        if (lane == 0) atomicAdd(&d_gsum[batch[node]], p + __ldg(&bf3[0]));
    }
}

__global__ void k_util(float* __restrict__ out) {
    int g = blockIdx.x * blockDim.x + threadIdx.x;
    if (g < G_GR) {
        float c = (float)d_gcnt[g];
        float u = d_gsum[g] / fmaxf(c, 1.0f);
        d_util[g] = u;
        out[P_PAIRS + g] = u;
    }
}

__global__ void k_pairs(const int* __restrict__ ia, const int* __restrict__ ib,
                        float* __restrict__ out) {
    int p = blockIdx.x * blockDim.x + threadIdx.x;
    if (p < P_PAIRS) {
        float x = d_util[ib[p]] - d_util[ia[p]];
        out[p] = 1.0f / (1.0f + expf(-x));
    }
}

// ---------------- launch ----------------------------------------------------
extern "C" void kernel_launch(void* const* d_in, const int* in_sizes, int n_in,
                              void* d_out, int out_size) {
    const float* x     = (const float*)d_in[0];
    const int*   ei    = (const int*)d_in[1];
    const int*   batch = (const int*)d_in[2];
    const int*   idx_a = (const int*)d_in[3];
    const int*   idx_b = (const int*)d_in[4];
    const float* W_in  = (const float*)d_in[5];
    const float* b_in  = (const float*)d_in[6];
    const float* W1    = (const float*)d_in[7];
    const float* b1    = (const float*)d_in[8];
    const float* W2    = (const float*)d_in[9];
    const float* b2    = (const float*)d_in[10];
    const float* Wf1   = (const float*)d_in[11];
    const float* bf1   = (const float*)d_in[12];
    const float* Wf2   = (const float*)d_in[13];
    const float* bf2   = (const float*)d_in[14];
    const float* Wf3   = (const float*)d_in[15];
    const float* bf3   = (const float*)d_in[16];
    float* out = (float*)d_out;

    static float* pg = nullptr;
    static float* ph = nullptr;
    if (!pg) {
        cudaGetSymbolAddress((void**)&pg, d_g);
        cudaGetSymbolAddress((void**)&ph, d_h);
        cudaFuncSetAttribute(k_gemm128<0>, cudaFuncAttributeMaxDynamicSharedMemorySize, 99328);
        cudaFuncSetAttribute(k_gemm128<1>, cudaFuncAttributeMaxDynamicSharedMemorySize, 99328);
    }

    const int nb = (N_NODES + 1023) / 1024;  // 98

    k_zero<<<(N_NODES + 255) / 256, 256>>>();
    k_count<<<(E_EDGES + 255) / 256, 256>>>(ei);
    k_scan1<<<nb, 1024>>>(N_NODES);
    k_scan2<<<1, 128>>>(nb);
    k_scan3<<<(N_NODES + 255) / 256, 256>>>(batch);
    k_fill<<<(E_EDGES + 255) / 256, 256>>>(ei);

    const int gemm_grid = (N_NODES + 63) / 64;  // 1563
    const int agg_grid  = (N_NODES + 7) / 8;    // 12500

    // layer 0: 9 -> 128
    k_gemm_in<<<2048, 128>>>(x, W_in, pg);
    k_agg<<<agg_grid, 256>>>(pg, b_in, ph);
    // layer 1
    k_gemm128<0><<<gemm_grid, 256, 99328>>>(ph, W1, nullptr, pg);
    k_agg<<<agg_grid, 256>>>(pg, b1, ph);
    // layer 2
    k_gemm128<0><<<gemm_grid, 256, 99328>>>(ph, W2, nullptr, pg);
    k_agg<<<agg_grid, 256>>>(pg, b2, ph);
    // head
    k_gemm128<1><<<gemm_grid, 256, 99328>>>(ph, Wf1, bf1, pg);
    k_final<<<agg_grid, 256>>>(pg, Wf2, bf2, Wf3, bf3, batch);
    k_util<<<(G_GR + 255) / 256, 256>>>(out);
    k_pairs<<<(P_PAIRS + 255) / 256, 256>>>(idx_a, idx_b, out);
}

// round 2
// speedup vs baseline: 2.0589x; 2.0589x over previous
#include <cuda_runtime.h>
#include <cuda_bf16.h>
#include <math.h>

#define N_NODES 100000
#define E_EDGES 1600000
#define G_GR    2000
#define P_PAIRS 4096
#define UDIM    128

// ---------------- scratch (static device globals; no allocation) -------------
__device__ float d_g[N_NODES * UDIM];     // 51.2 MB ping
__device__ float d_h[N_NODES * UDIM];     // 51.2 MB pong
__device__ int   d_counts[N_NODES];
__device__ int   d_startA[N_NODES];
__device__ int   d_cursor[N_NODES];
__device__ int   d_bsums[128];
__device__ int   d_boffs[128];
__device__ float d_dinv[N_NODES];
__device__ int   d_esrc[E_EDGES];         // edge srcs sorted by dst (CSR payload)
__device__ float d_gsum[G_GR];
__device__ int   d_gcnt[G_GR];
__device__ float d_util[G_GR];

// ---------------- init / CSR build ------------------------------------------
__global__ void k_zero() {
    int i = blockIdx.x * blockDim.x + threadIdx.x;
    if (i < N_NODES) d_counts[i] = 0;
    if (i < G_GR) { d_gsum[i] = 0.0f; d_gcnt[i] = 0; }
}

__global__ void k_count(const int* __restrict__ ei) {
    int e = blockIdx.x * blockDim.x + threadIdx.x;
    if (e < E_EDGES) atomicAdd(&d_counts[ei[E_EDGES + e]], 1);
}

__global__ void k_scan1(int n) {
    __shared__ int wsum[32];
    int i = blockIdx.x * 1024 + threadIdx.x;
    int lane = threadIdx.x & 31, w = threadIdx.x >> 5;
    int v = (i < n) ? d_counts[i] : 0;
    int x = v;
#pragma unroll
    for (int o = 1; o < 32; o <<= 1) {
        int y = __shfl_up_sync(0xffffffffu, x, o);
        if (lane >= o) x += y;
    }
    if (lane == 31) wsum[w] = x;
    __syncthreads();
    if (w == 0) {
        int s = wsum[lane];
        int xx = s;
#pragma unroll
        for (int o = 1; o < 32; o <<= 1) {
            int y = __shfl_up_sync(0xffffffffu, xx, o);
            if (lane >= o) xx += y;
        }
        if (lane == 31) d_bsums[blockIdx.x] = xx;   // block total
        wsum[lane] = xx - s;                        // exclusive warp offset
    }
    __syncthreads();
    int excl = x - v + wsum[w];
    if (i < n) d_startA[i] = excl;
}

__global__ void k_scan2(int nb) {
    __shared__ int wsum[4];
    int t = threadIdx.x, lane = t & 31, w = t >> 5;
    int v = (t < nb) ? d_bsums[t] : 0;
    int x = v;
#pragma unroll
    for (int o = 1; o < 32; o <<= 1) {
        int y = __shfl_up_sync(0xffffffffu, x, o);
        if (lane >= o) x += y;
    }
    if (lane == 31) wsum[w] = x;
    __syncthreads();
    if (t == 0) {
        int a = 0;
#pragma unroll
        for (int i = 0; i < 4; i++) { int tmp = wsum[i]; wsum[i] = a; a += tmp; }
    }
    __syncthreads();
    if (t < nb) d_boffs[t] = x - v + wsum[w];
}

__global__ void k_scan3(const int* __restrict__ batch) {
    int i = blockIdx.x * blockDim.x + threadIdx.x;
    if (i < N_NODES) {
        int s = d_startA[i] + d_boffs[i >> 10];
        d_startA[i] = s;
        d_cursor[i] = s;
        d_dinv[i] = rsqrtf((float)d_counts[i] + 1.0f);
        atomicAdd(&d_gcnt[batch[i]], 1);
    }
}

__global__ void k_fill(const int* __restrict__ ei) {
    int e = blockIdx.x * blockDim.x + threadIdx.x;
    if (e < E_EDGES) {
        int s = ei[e];
        int d = ei[E_EDGES + e];
        int p = atomicAdd(&d_cursor[d], 1);
        d_esrc[p] = s;
    }
}

// ---------------- GEMMs -----------------------------------------------------
// first layer: g = dinv * (x[N,9] @ W_in[9,128])
__global__ void k_gemm_in(const float* __restrict__ x, const float* __restrict__ W,
                          float* __restrict__ g) {
    __shared__ float Ws[9 * 128];
    for (int i = threadIdx.x; i < 9 * 128; i += 128) Ws[i] = W[i];
    __syncthreads();
    int j = threadIdx.x;
    for (int row = blockIdx.x; row < N_NODES; row += gridDim.x) {
        float acc = 0.0f;
#pragma unroll
        for (int k = 0; k < 9; k++)
            acc += __ldg(&x[row * 9 + k]) * Ws[k * 128 + j];
        g[row * 128 + j] = d_dinv[row] * acc;
    }
}

__device__ __forceinline__ unsigned f2tf32(float f) {
    unsigned u;
    asm("cvt.rna.tf32.f32 %0, %1;" : "=r"(u) : "f"(f));
    return u;
}

// Tensor-core tf32 GEMM: C[N,128] = A[N,128] @ W[128,128] (+ epilogue)
// MODE 0: C = dinv * (A@W)      MODE 1: C = tanh(A@W + bias)
// Tile: BM=128, full K=128, full N=128. 8 warps in 4(m) x 2(n) layout.
// Each warp: 32 rows x 64 cols = 2 m-frags x 8 n-frags of m16n8k8.
template <int MODE>
__global__ __launch_bounds__(256, 1) void k_gemm_tc(
        const float* __restrict__ A, const float* __restrict__ W,
        const float* __restrict__ bias, float* __restrict__ C) {
    extern __shared__ unsigned smu[];
    unsigned* As = smu;               // [128][132] row-major (row, k)
    unsigned* Wt = smu + 128 * 132;   // [128][132] n-major  (n, k)
    const int t = threadIdx.x;
    const int row0 = blockIdx.x * 128;

    // load W transposed (k,n)->(n,k), convert to tf32
    for (int i = t; i < 128 * 128; i += 256) {
        int k = i >> 7, n = i & 127;
        Wt[n * 132 + k] = f2tf32(__ldg(&W[i]));
    }
    // load A tile (zero-padded past N), convert to tf32
    for (int i = t; i < 128 * 32; i += 256) {
        int r = i >> 5, c4 = (i & 31) << 2;
        float4 v = make_float4(0.f, 0.f, 0.f, 0.f);
        if (row0 + r < N_NODES) v = ((const float4*)A)[(size_t)(row0 + r) * 32 + (i & 31)];
        uint4 u;
        u.x = f2tf32(v.x); u.y = f2tf32(v.y); u.z = f2tf32(v.z); u.w = f2tf32(v.w);
        *(uint4*)&As[r * 132 + c4] = u;
    }
    __syncthreads();

    const int w = t >> 5, lane = t & 31;
    const int wm = w & 3, wn = w >> 2;     // wm: 4 m-tiles of 32 rows, wn: 2 n-tiles of 64
    const int rbase = wm * 32;
    const int cbase = wn * 64;
    const int gid = lane >> 2, tig = lane & 3;

    float acc[2][8][4];
#pragma unroll
    for (int mi = 0; mi < 2; mi++)
#pragma unroll
        for (int ni = 0; ni < 8; ni++)
#pragma unroll
            for (int q = 0; q < 4; q++) acc[mi][ni][q] = 0.0f;

#pragma unroll 2
    for (int ks = 0; ks < 16; ks++) {
        const int k0 = ks * 8;
        unsigned a[2][4];
#pragma unroll
        for (int mi = 0; mi < 2; mi++) {
            int r = rbase + mi * 16 + gid;
            a[mi][0] = As[r * 132 + k0 + tig];
            a[mi][1] = As[(r + 8) * 132 + k0 + tig];
            a[mi][2] = As[r * 132 + k0 + tig + 4];
            a[mi][3] = As[(r + 8) * 132 + k0 + tig + 4];
        }
        unsigned b[8][2];
#pragma unroll
        for (int ni = 0; ni < 8; ni++) {
            int n = cbase + ni * 8 + gid;
            b[ni][0] = Wt[n * 132 + k0 + tig];
            b[ni][1] = Wt[n * 132 + k0 + tig + 4];
        }
#pragma unroll
        for (int mi = 0; mi < 2; mi++)
#pragma unroll
            for (int ni = 0; ni < 8; ni++)
                asm volatile(
                    "mma.sync.aligned.m16n8k8.row.col.f32.tf32.tf32.f32 "
                    "{%0,%1,%2,%3}, {%4,%5,%6,%7}, {%8,%9}, {%0,%1,%2,%3};"
                    : "+f"(acc[mi][ni][0]), "+f"(acc[mi][ni][1]),
                      "+f"(acc[mi][ni][2]), "+f"(acc[mi][ni][3])
                    : "r"(a[mi][0]), "r"(a[mi][1]), "r"(a[mi][2]), "r"(a[mi][3]),
                      "r"(b[ni][0]), "r"(b[ni][1]));
    }

    // epilogue
#pragma unroll
    for (int mi = 0; mi < 2; mi++) {
#pragma unroll
        for (int half = 0; half < 2; half++) {
            int r = row0 + rbase + mi * 16 + gid + half * 8;
            if (r < N_NODES) {
                float scale = (MODE == 0) ? d_dinv[r] : 1.0f;
#pragma unroll
                for (int ni = 0; ni < 8; ni++) {
                    int c = cbase + ni * 8 + tig * 2;
                    float v0 = acc[mi][ni][half * 2 + 0];
                    float v1 = acc[mi][ni][half * 2 + 1];
                    if (MODE == 0) { v0 *= scale; v1 *= scale; }
                    else {
                        v0 = tanhf(v0 + __ldg(&bias[c]));
                        v1 = tanhf(v1 + __ldg(&bias[c + 1]));
                    }
                    *(float2*)&C[(size_t)r * 128 + c] = make_float2(v0, v1);
                }
            }
        }
    }
}

// ---------------- edge aggregation ------------------------------------------
// h[d] = tanh( dinv[d] * ( g[d] + sum_{e in CSR(d)} g[src_e] ) + b )
__global__ void k_agg(const float* __restrict__ gbuf, const float* __restrict__ bias,
                      float* __restrict__ hout) {
    int gw = (blockIdx.x * blockDim.x + threadIdx.x) >> 5;
    int lane = threadIdx.x & 31;
    if (gw >= N_NODES) return;
    int d = gw;

    const float4* g4 = (const float4*)gbuf;
    float4 acc = g4[(size_t)d * 32 + lane];
    float4 acc2 = make_float4(0.f, 0.f, 0.f, 0.f);

    int s0 = d_startA[d];
    int cnt = d_counts[d];
    for (int base = 0; base < cnt; base += 32) {
        int s = (base + lane < cnt) ? d_esrc[s0 + base + lane] : 0;
        int m = min(32, cnt - base);
        int i = 0;
        for (; i + 1 < m; i += 2) {
            int ss0 = __shfl_sync(0xffffffffu, s, i);
            int ss1 = __shfl_sync(0xffffffffu, s, i + 1);
            float4 v0 = g4[(size_t)ss0 * 32 + lane];
            float4 v1 = g4[(size_t)ss1 * 32 + lane];
            acc.x += v0.x; acc.y += v0.y; acc.z += v0.z; acc.w += v0.w;
            acc2.x += v1.x; acc2.y += v1.y; acc2.z += v1.z; acc2.w += v1.w;
        }
        if (i < m) {
            int ss = __shfl_sync(0xffffffffu, s, i);
            float4 v = g4[(size_t)ss * 32 + lane];
            acc.x += v.x; acc.y += v.y; acc.z += v.z; acc.w += v.w;
        }
    }
    acc.x += acc2.x; acc.y += acc2.y; acc.z += acc2.z; acc.w += acc2.w;

    float di = d_dinv[d];
    float4 b = ((const float4*)bias)[lane];
    float4 o;
    o.x = tanhf(di * acc.x + b.x);
    o.y = tanhf(di * acc.y + b.y);
    o.z = tanhf(di * acc.z + b.z);
    o.w = tanhf(di * acc.w + b.w);
    ((float4*)hout)[(size_t)d * 32 + lane] = o;
}

// ---------------- head: Wf2(128->32) tanh, Wf3(32->1), per-graph sum --------
__global__ void k_final(const float* __restrict__ h2, const float* __restrict__ Wf2,
                        const float* __restrict__ bf2, const float* __restrict__ Wf3,
                        const float* __restrict__ bf3, const int* __restrict__ batch) {
    __shared__ float Wf2s[128 * 32];
    __shared__ float Hs[8][132];
    __shared__ float bf2s[32];
    __shared__ float wf3s[32];
    int t = threadIdx.x;
    for (int i = t; i < 128 * 32; i += 256) Wf2s[i] = Wf2[i];
    if (t < 32) { bf2s[t] = bf2[t]; wf3s[t] = Wf3[t]; }

    int nodeBase = blockIdx.x * 8;
    for (int i = t; i < 8 * 32; i += 256) {
        int r = i >> 5, c4 = i & 31;
        int nd = nodeBase + r;
        float4 v = make_float4(0.f, 0.f, 0.f, 0.f);
        if (nd < N_NODES) v = ((const float4*)h2)[(size_t)nd * 32 + c4];
        *((float4*)&Hs[r][c4 * 4]) = v;
    }
    __syncthreads();

    int lane = t & 31, w = t >> 5;
    int node = nodeBase + w;
    if (node < N_NODES) {
        float acc = 0.0f;
#pragma unroll 8
        for (int k = 0; k < 128; k++) acc += Hs[w][k] * Wf2s[k * 32 + lane];
        float tt = tanhf(acc + bf2s[lane]);
        float p = tt * wf3s[lane];
#pragma unroll
        for (int o = 16; o > 0; o >>= 1) p += __shfl_down_sync(0xffffffffu, p, o);
        if (lane == 0) atomicAdd(&d_gsum[batch[node]], p + __ldg(&bf3[0]));
    }
}

__global__ void k_util(float* __restrict__ out) {
    int g = blockIdx.x * blockDim.x + threadIdx.x;
    if (g < G_GR) {
        float c = (float)d_gcnt[g];
        float u = d_gsum[g] / fmaxf(c, 1.0f);
        d_util[g] = u;
        out[P_PAIRS + g] = u;
    }
}

__global__ void k_pairs(const int* __restrict__ ia, const int* __restrict__ ib,
                        float* __restrict__ out) {
    int p = blockIdx.x * blockDim.x + threadIdx.x;
    if (p < P_PAIRS) {
        float x = d_util[ib[p]] - d_util[ia[p]];
        out[p] = 1.0f / (1.0f + expf(-x));
    }
}

// ---------------- launch ----------------------------------------------------
extern "C" void kernel_launch(void* const* d_in, const int* in_sizes, int n_in,
                              void* d_out, int out_size) {
    const float* x     = (const float*)d_in[0];
    const int*   ei    = (const int*)d_in[1];
    const int*   batch = (const int*)d_in[2];
    const int*   idx_a = (const int*)d_in[3];
    const int*   idx_b = (const int*)d_in[4];
    const float* W_in  = (const float*)d_in[5];
    const float* b_in  = (const float*)d_in[6];
    const float* W1    = (const float*)d_in[7];
    const float* b1    = (const float*)d_in[8];
    const float* W2    = (const float*)d_in[9];
    const float* b2    = (const float*)d_in[10];
    const float* Wf1   = (const float*)d_in[11];
    const float* bf1   = (const float*)d_in[12];
    const float* Wf2   = (const float*)d_in[13];
    const float* bf2   = (const float*)d_in[14];
    const float* Wf3   = (const float*)d_in[15];
    const float* bf3   = (const float*)d_in[16];
    float* out = (float*)d_out;

    static float* pg = nullptr;
    static float* ph = nullptr;
    if (!pg) {
        cudaGetSymbolAddress((void**)&pg, d_g);
        cudaGetSymbolAddress((void**)&ph, d_h);
        cudaFuncSetAttribute(k_gemm_tc<0>, cudaFuncAttributeMaxDynamicSharedMemorySize, 135168);
        cudaFuncSetAttribute(k_gemm_tc<1>, cudaFuncAttributeMaxDynamicSharedMemorySize, 135168);
    }

    const int nb = (N_NODES + 1023) / 1024;  // 98

    k_zero<<<(N_NODES + 255) / 256, 256>>>();
    k_count<<<(E_EDGES + 255) / 256, 256>>>(ei);
    k_scan1<<<nb, 1024>>>(N_NODES);
    k_scan2<<<1, 128>>>(nb);
    k_scan3<<<(N_NODES + 255) / 256, 256>>>(batch);
    k_fill<<<(E_EDGES + 255) / 256, 256>>>(ei);

    const int tc_grid  = (N_NODES + 127) / 128;  // 782
    const int agg_grid = (N_NODES + 7) / 8;      // 12500

    // layer 0: 9 -> 128
    k_gemm_in<<<2048, 128>>>(x, W_in, pg);
    k_agg<<<agg_grid, 256>>>(pg, b_in, ph);
    // layer 1
    k_gemm_tc<0><<<tc_grid, 256, 135168>>>(ph, W1, nullptr, pg);
    k_agg<<<agg_grid, 256>>>(pg, b1, ph);
    // layer 2
    k_gemm_tc<0><<<tc_grid, 256, 135168>>>(ph, W2, nullptr, pg);
    k_agg<<<agg_grid, 256>>>(pg, b2, ph);
    // head
    k_gemm_tc<1><<<tc_grid, 256, 135168>>>(ph, Wf1, bf1, pg);
    k_final<<<agg_grid, 256>>>(pg, Wf2, bf2, Wf3, bf3, batch);
    k_util<<<(G_GR + 255) / 256, 256>>>(out);
    k_pairs<<<(P_PAIRS + 255) / 256, 256>>>(idx_a, idx_b, out);
}

// round 5
// speedup vs baseline: 3.1189x; 1.5149x over previous
#include <cuda_runtime.h>
#include <cuda_fp16.h>
#include <math.h>

#define N_NODES 100000
#define E_EDGES 1600000
#define G_GR    2000
#define P_PAIRS 4096
#define UDIM    128

// ---------------- scratch (static device globals; no allocation) -------------
__device__ __half d_g[N_NODES * UDIM];    // 25.6 MB ping (fp16 features)
__device__ __half d_h[N_NODES * UDIM];    // 25.6 MB pong
__device__ int    d_counts[N_NODES];
__device__ int    d_startA[N_NODES];
__device__ int    d_cursor[N_NODES];
__device__ int    d_bsums[128];
__device__ int    d_boffs[128];
__device__ float  d_dinv[N_NODES];
__device__ int    d_esrc[E_EDGES];        // edge srcs sorted by dst (CSR payload)
__device__ float  d_gsum[G_GR];
__device__ int    d_gcnt[G_GR];
__device__ float  d_util[G_GR];

// ---------------- helpers ----------------------------------------------------
__device__ __forceinline__ float4 h4_to_f4(uint2 u) {
    __half2 p0 = *(__half2*)&u.x;
    __half2 p1 = *(__half2*)&u.y;
    float2 f0 = __half22float2(p0), f1 = __half22float2(p1);
    return make_float4(f0.x, f0.y, f1.x, f1.y);
}
__device__ __forceinline__ uint2 f4_to_h4(float4 v) {
    __half2 p0 = __floats2half2_rn(v.x, v.y);
    __half2 p1 = __floats2half2_rn(v.z, v.w);
    uint2 u;
    u.x = *(unsigned*)&p0;
    u.y = *(unsigned*)&p1;
    return u;
}

// ---------------- init / CSR build ------------------------------------------
__global__ void k_zero() {
    int i = blockIdx.x * blockDim.x + threadIdx.x;
    if (i < N_NODES) d_counts[i] = 0;
    if (i < G_GR) { d_gsum[i] = 0.0f; d_gcnt[i] = 0; }
}

__global__ void k_count(const int* __restrict__ ei) {
    int e = blockIdx.x * blockDim.x + threadIdx.x;
    if (e < E_EDGES) atomicAdd(&d_counts[__ldg(&ei[E_EDGES + e])], 1);
}

__global__ void k_scan1(int n) {
    __shared__ int wsum[32];
    int i = blockIdx.x * 1024 + threadIdx.x;
    int lane = threadIdx.x & 31, w = threadIdx.x >> 5;
    int v = (i < n) ? d_counts[i] : 0;
    int x = v;
#pragma unroll
    for (int o = 1; o < 32; o <<= 1) {
        int y = __shfl_up_sync(0xffffffffu, x, o);
        if (lane >= o) x += y;
    }
    if (lane == 31) wsum[w] = x;
    __syncthreads();
    if (w == 0) {
        int s = wsum[lane];
        int xx = s;
#pragma unroll
        for (int o = 1; o < 32; o <<= 1) {
            int y = __shfl_up_sync(0xffffffffu, xx, o);
            if (lane >= o) xx += y;
        }
        if (lane == 31) d_bsums[blockIdx.x] = xx;   // block total
        wsum[lane] = xx - s;                        // exclusive warp offset
    }
    __syncthreads();
    int excl = x - v + wsum[w];
    if (i < n) d_startA[i] = excl;
}

__global__ void k_scan2(int nb) {
    __shared__ int wsum[4];
    int t = threadIdx.x, lane = t & 31, w = t >> 5;
    int v = (t < nb) ? d_bsums[t] : 0;
    int x = v;
#pragma unroll
    for (int o = 1; o < 32; o <<= 1) {
        int y = __shfl_up_sync(0xffffffffu, x, o);
        if (lane >= o) x += y;
    }
    if (lane == 31) wsum[w] = x;
    __syncthreads();
    if (t == 0) {
        int a = 0;
#pragma unroll
        for (int i = 0; i < 4; i++) { int tmp = wsum[i]; wsum[i] = a; a += tmp; }
    }
    __syncthreads();
    if (t < nb) d_boffs[t] = x - v + wsum[w];
}

__global__ void k_scan3(const int* __restrict__ batch) {
    int i = blockIdx.x * blockDim.x + threadIdx.x;
    if (i < N_NODES) {
        int s = d_startA[i] + d_boffs[i >> 10];
        d_startA[i] = s;
        d_cursor[i] = s;
        d_dinv[i] = rsqrtf((float)d_counts[i] + 1.0f);
        atomicAdd(&d_gcnt[batch[i]], 1);
    }
}

__global__ void k_fill(const int* __restrict__ ei) {
    int e = blockIdx.x * blockDim.x + threadIdx.x;
    if (e < E_EDGES) {
        int s = __ldg(&ei[e]);
        int d = __ldg(&ei[E_EDGES + e]);
        int p = atomicAdd(&d_cursor[d], 1);
        d_esrc[p] = s;
    }
}

// ---------------- GEMMs -----------------------------------------------------
// first layer: g = dinv * (x[N,9] @ W_in[9,128]) -> fp16
__global__ void k_gemm_in(const float* __restrict__ x, const float* __restrict__ W,
                          __half* __restrict__ g) {
    __shared__ float Ws[9 * 128];
    for (int i = threadIdx.x; i < 9 * 128; i += 128) Ws[i] = W[i];
    __syncthreads();
    int j = threadIdx.x;
    for (int row = blockIdx.x; row < N_NODES; row += gridDim.x) {
        float acc = 0.0f;
#pragma unroll
        for (int k = 0; k < 9; k++)
            acc += __ldg(&x[row * 9 + k]) * Ws[k * 128 + j];
        g[row * 128 + j] = __float2half(d_dinv[row] * acc);
    }
}

// fp16 tensor-core GEMM: C[N,128] = A[N,128] @ W[128,128] (+ epilogue), fp32 accum
// MODE 0: C = dinv * (A@W)      MODE 1: C = tanh(A@W + bias)
// Tile: BM=128, full K=128, full N=128. 8 warps in 4(m) x 2(n) layout.
// Each warp: 32 rows x 64 cols = 2 m-frags x 8 n-frags of m16n8k16.
#define HSTRIDE 136
template <int MODE>
__global__ __launch_bounds__(256) void k_gemm_tc(
        const __half* __restrict__ A, const float* __restrict__ W,
        const float* __restrict__ bias, __half* __restrict__ C) {
    extern __shared__ __half sm[];
    __half* As = sm;                  // [128][136] (row, k)
    __half* Wt = sm + 128 * HSTRIDE;  // [128][136] (n, k)
    const int t = threadIdx.x;
    const int row0 = blockIdx.x * 128;

    // W (k,n) fp32 -> Wt (n,k) fp16
    for (int i = t; i < 128 * 128; i += 256) {
        int k = i >> 7, n = i & 127;
        Wt[n * HSTRIDE + k] = __float2half(__ldg(&W[i]));
    }
    // A tile fp16 direct copy (zero-pad past N)
    const uint4* A4 = (const uint4*)A;   // 8 halves each
    for (int i = t; i < 128 * 16; i += 256) {
        int r = i >> 4, c = i & 15;
        uint4 v = make_uint4(0u, 0u, 0u, 0u);
        if (row0 + r < N_NODES) v = A4[(size_t)(row0 + r) * 16 + c];
        *(uint4*)&As[r * HSTRIDE + c * 8] = v;
    }
    __syncthreads();

    const int w = t >> 5, lane = t & 31;
    const int wm = w & 3, wn = w >> 2;
    const int rbase = wm * 32;
    const int cbase = wn * 64;
    const int gid = lane >> 2, tig = lane & 3;

    float acc[2][8][4];
#pragma unroll
    for (int mi = 0; mi < 2; mi++)
#pragma unroll
        for (int ni = 0; ni < 8; ni++)
#pragma unroll
            for (int q = 0; q < 4; q++) acc[mi][ni][q] = 0.0f;

#pragma unroll
    for (int ks = 0; ks < 8; ks++) {
        const int k0 = ks * 16;
        unsigned a[2][4];
#pragma unroll
        for (int mi = 0; mi < 2; mi++) {
            int r = rbase + mi * 16 + gid;
            a[mi][0] = *(const unsigned*)&As[r * HSTRIDE + k0 + tig * 2];
            a[mi][1] = *(const unsigned*)&As[(r + 8) * HSTRIDE + k0 + tig * 2];
            a[mi][2] = *(const unsigned*)&As[r * HSTRIDE + k0 + 8 + tig * 2];
            a[mi][3] = *(const unsigned*)&As[(r + 8) * HSTRIDE + k0 + 8 + tig * 2];
        }
        unsigned b[8][2];
#pragma unroll
        for (int ni = 0; ni < 8; ni++) {
            int n = cbase + ni * 8 + gid;
            b[ni][0] = *(const unsigned*)&Wt[n * HSTRIDE + k0 + tig * 2];
            b[ni][1] = *(const unsigned*)&Wt[n * HSTRIDE + k0 + 8 + tig * 2];
        }
#pragma unroll
        for (int mi = 0; mi < 2; mi++)
#pragma unroll
            for (int ni = 0; ni < 8; ni++)
                asm volatile(
                    "mma.sync.aligned.m16n8k16.row.col.f32.f16.f16.f32 "
                    "{%0,%1,%2,%3}, {%4,%5,%6,%7}, {%8,%9}, {%0,%1,%2,%3};"
                    : "+f"(acc[mi][ni][0]), "+f"(acc[mi][ni][1]),
                      "+f"(acc[mi][ni][2]), "+f"(acc[mi][ni][3])
                    : "r"(a[mi][0]), "r"(a[mi][1]), "r"(a[mi][2]), "r"(a[mi][3]),
                      "r"(b[ni][0]), "r"(b[ni][1]));
    }

    // epilogue -> fp16
#pragma unroll
    for (int mi = 0; mi < 2; mi++) {
#pragma unroll
        for (int hf = 0; hf < 2; hf++) {
            int r = row0 + rbase + mi * 16 + gid + hf * 8;
            if (r < N_NODES) {
                float scale = (MODE == 0) ? d_dinv[r] : 1.0f;
#pragma unroll
                for (int ni = 0; ni < 8; ni++) {
                    int c = cbase + ni * 8 + tig * 2;
                    float v0 = acc[mi][ni][hf * 2 + 0];
                    float v1 = acc[mi][ni][hf * 2 + 1];
                    if (MODE == 0) { v0 *= scale; v1 *= scale; }
                    else {
                        v0 = tanhf(v0 + __ldg(&bias[c]));
                        v1 = tanhf(v1 + __ldg(&bias[c + 1]));
                    }
                    *(__half2*)&C[(size_t)r * 128 + c] = __floats2half2_rn(v0, v1);
                }
            }
        }
    }
}

// ---------------- edge aggregation ------------------------------------------
// h[d] = tanh( dinv[d] * ( g[d] + sum_{e in CSR(d)} g[src_e] ) + b )   (fp16 io)
__global__ void k_agg(const __half* __restrict__ gbuf, const float* __restrict__ bias,
                      __half* __restrict__ hout) {
    int gw = (blockIdx.x * blockDim.x + threadIdx.x) >> 5;
    int lane = threadIdx.x & 31;
    if (gw >= N_NODES) return;
    int d = gw;

    const uint2* g2 = (const uint2*)gbuf;    // 4 halves per lane
    float4 acc = h4_to_f4(g2[(size_t)d * 32 + lane]);
    float4 acc2 = make_float4(0.f, 0.f, 0.f, 0.f);

    int s0 = d_startA[d];
    int cnt = d_counts[d];
    for (int base = 0; base < cnt; base += 32) {
        int s = (base + lane < cnt) ? d_esrc[s0 + base + lane] : 0;
        int m = min(32, cnt - base);
        int i = 0;
        for (; i + 1 < m; i += 2) {
            int ss0 = __shfl_sync(0xffffffffu, s, i);
            int ss1 = __shfl_sync(0xffffffffu, s, i + 1);
            float4 v0 = h4_to_f4(g2[(size_t)ss0 * 32 + lane]);
            float4 v1 = h4_to_f4(g2[(size_t)ss1 * 32 + lane]);
            acc.x += v0.x; acc.y += v0.y; acc.z += v0.z; acc.w += v0.w;
            acc2.x += v1.x; acc2.y += v1.y; acc2.z += v1.z; acc2.w += v1.w;
        }
        if (i < m) {
            int ss = __shfl_sync(0xffffffffu, s, i);
            float4 v = h4_to_f4(g2[(size_t)ss * 32 + lane]);
            acc.x += v.x; acc.y += v.y; acc.z += v.z; acc.w += v.w;
        }
    }
    acc.x += acc2.x; acc.y += acc2.y; acc.z += acc2.z; acc.w += acc2.w;

    float di = d_dinv[d];
    float4 b = ((const float4*)bias)[lane];
    float4 o;
    o.x = tanhf(di * acc.x + b.x);
    o.y = tanhf(di * acc.y + b.y);
    o.z = tanhf(di * acc.z + b.z);
    o.w = tanhf(di * acc.w + b.w);
    ((uint2*)hout)[(size_t)d * 32 + lane] = f4_to_h4(o);
}

// ---------------- head: Wf2(128->32) tanh, Wf3(32->1), per-graph sum --------
__global__ void k_final(const __half* __restrict__ h2, const float* __restrict__ Wf2,
                        const float* __restrict__ bf2, const float* __restrict__ Wf3,
                        const float* __restrict__ bf3, const int* __restrict__ batch) {
    __shared__ float Wf2s[128 * 32];
    __shared__ float Hs[8][132];
    __shared__ float bf2s[32];
    __shared__ float wf3s[32];
    int t = threadIdx.x;
    for (int i = t; i < 128 * 32; i += 256) Wf2s[i] = Wf2[i];
    if (t < 32) { bf2s[t] = bf2[t]; wf3s[t] = Wf3[t]; }

    int nodeBase = blockIdx.x * 8;
    for (int i = t; i < 8 * 32; i += 256) {
        int r = i >> 5, c4 = i & 31;
        int nd = nodeBase + r;
        uint2 v = make_uint2(0u, 0u);
        if (nd < N_NODES) v = ((const uint2*)h2)[(size_t)nd * 32 + c4];
        *((float4*)&Hs[r][c4 * 4]) = h4_to_f4(v);
    }
    __syncthreads();

    int lane = t & 31, w = t >> 5;
    int node = nodeBase + w;
    if (node < N_NODES) {
        float acc = 0.0f;
#pragma unroll 8
        for (int k = 0; k < 128; k++) acc += Hs[w][k] * Wf2s[k * 32 + lane];
        float tt = tanhf(acc + bf2s[lane]);
        float p = tt * wf3s[lane];
#pragma unroll
        for (int o = 16; o > 0; o >>= 1) p += __shfl_down_sync(0xffffffffu, p, o);
        if (lane == 0) atomicAdd(&d_gsum[batch[node]], p + __ldg(&bf3[0]));
    }
}

__global__ void k_util(float* __restrict__ out) {
    int g = blockIdx.x * blockDim.x + threadIdx.x;
    if (g < G_GR) {
        float c = (float)d_gcnt[g];
        float u = d_gsum[g] / fmaxf(c, 1.0f);
        d_util[g] = u;
        out[P_PAIRS + g] = u;
    }
}

__global__ void k_pairs(const int* __restrict__ ia, const int* __restrict__ ib,
                        float* __restrict__ out) {
    int p = blockIdx.x * blockDim.x + threadIdx.x;
    if (p < P_PAIRS) {
        float x = d_util[ib[p]] - d_util[ia[p]];
        out[p] = 1.0f / (1.0f + expf(-x));
    }
}

// ---------------- launch ----------------------------------------------------
extern "C" void kernel_launch(void* const* d_in, const int* in_sizes, int n_in,
                              void* d_out, int out_size) {
    const float* x     = (const float*)d_in[0];
    const int*   ei    = (const int*)d_in[1];
    const int*   batch = (const int*)d_in[2];
    const int*   idx_a = (const int*)d_in[3];
    const int*   idx_b = (const int*)d_in[4];
    const float* W_in  = (const float*)d_in[5];
    const float* b_in  = (const float*)d_in[6];
    const float* W1    = (const float*)d_in[7];
    const float* b1    = (const float*)d_in[8];
    const float* W2    = (const float*)d_in[9];
    const float* b2    = (const float*)d_in[10];
    const float* Wf1   = (const float*)d_in[11];
    const float* bf1   = (const float*)d_in[12];
    const float* Wf2   = (const float*)d_in[13];
    const float* bf2   = (const float*)d_in[14];
    const float* Wf3   = (const float*)d_in[15];
    const float* bf3   = (const float*)d_in[16];
    float* out = (float*)d_out;

    static __half* pg = nullptr;
    static __half* ph = nullptr;
    if (!pg) {
        cudaGetSymbolAddress((void**)&pg, d_g);
        cudaGetSymbolAddress((void**)&ph, d_h);
        cudaFuncSetAttribute(k_gemm_tc<0>, cudaFuncAttributeMaxDynamicSharedMemorySize, 2 * 128 * HSTRIDE * 2);
        cudaFuncSetAttribute(k_gemm_tc<1>, cudaFuncAttributeMaxDynamicSharedMemorySize, 2 * 128 * HSTRIDE * 2);
    }
    const int smem_tc = 2 * 128 * HSTRIDE * 2;   // 69632 B

    const int nb = (N_NODES + 1023) / 1024;  // 98

    k_zero<<<(N_NODES + 255) / 256, 256>>>();
    k_count<<<(E_EDGES + 255) / 256, 256>>>(ei);
    k_scan1<<<nb, 1024>>>(N_NODES);
    k_scan2<<<1, 128>>>(nb);
    k_scan3<<<(N_NODES + 255) / 256, 256>>>(batch);
    k_fill<<<(E_EDGES + 255) / 256, 256>>>(ei);

    const int tc_grid  = (N_NODES + 127) / 128;  // 782
    const int agg_grid = (N_NODES + 7) / 8;      // 12500

    // layer 0: 9 -> 128
    k_gemm_in<<<2048, 128>>>(x, W_in, pg);
    k_agg<<<agg_grid, 256>>>(pg, b_in, ph);
    // layer 1
    k_gemm_tc<0><<<tc_grid, 256, smem_tc>>>(ph, W1, nullptr, pg);
    k_agg<<<agg_grid, 256>>>(pg, b1, ph);
    // layer 2
    k_gemm_tc<0><<<tc_grid, 256, smem_tc>>>(ph, W2, nullptr, pg);
    k_agg<<<agg_grid, 256>>>(pg, b2, ph);
    // head
    k_gemm_tc<1><<<tc_grid, 256, smem_tc>>>(ph, Wf1, bf1, pg);
    k_final<<<agg_grid, 256>>>(pg, Wf2, bf2, Wf3, bf3, batch);
    k_util<<<(G_GR + 255) / 256, 256>>>(out);
    k_pairs<<<(P_PAIRS + 255) / 256, 256>>>(idx_a, idx_b, out);
}